// round 15
// baseline (speedup 1.0000x reference)
#include <cuda_runtime.h>
#include <cuda_fp16.h>
#include <cstdint>

#define NB     16
#define NMEDIA 4096
#define NLAT   64
#define NKV    4160
#define DIM    1024
#define INNER  1024
#define NHEADS 16
#define DHEAD  64
#define SPLIT  5
#define TILES_PER 13   // 65 K-tiles of 64 / SPLIT

// ---------------- scratch (static device globals; no runtime allocation) ----------------
__device__ __half g_kvin [(size_t)NB*NKV*DIM];
__device__ __half g_lat16[(size_t)NB*NLAT*DIM];
__device__ __half g_q16  [(size_t)NB*NLAT*INNER];
__device__ __half g_kv16 [(size_t)NB*NKV*2*INNER];
__device__ __half g_ao16 [(size_t)NB*NLAT*INNER];
__device__ __half g_wq16 [(size_t)DIM*INNER];
__device__ __half g_wkv16[(size_t)DIM*2*INNER];    // Wkv fp16 [K][N]
__device__ __half g_wout16[(size_t)INNER*DIM];
__device__ float  g_opart[(size_t)SPLIT*NB*NLAT*INNER];
__device__ float  g_mlp  [(size_t)SPLIT*NB*NLAT*NHEADS*2];

// ---------------- helpers ----------------
__device__ __forceinline__ void cp_async16(uint32_t smem_dst, const void* gsrc) {
    asm volatile("cp.async.cg.shared.global [%0], [%1], 16;\n" :: "r"(smem_dst), "l"(gsrc));
}
__device__ __forceinline__ void cp_commit() { asm volatile("cp.async.commit_group;\n" ::); }
__device__ __forceinline__ void cp_wait1()  { asm volatile("cp.async.wait_group 1;\n" ::: "memory"); }
__device__ __forceinline__ void cp_wait0()  { asm volatile("cp.async.wait_group 0;\n" ::: "memory"); }

// ---------------- weight conversion fp32 -> fp16 ----------------
__global__ void cvt_weights(const float* __restrict__ Wq,
                            const float* __restrict__ Wkv,
                            const float* __restrict__ Wout) {
    int i = blockIdx.x * blockDim.x + threadIdx.x;
    const int n1 = DIM*INNER;
    const int n2 = DIM*2*INNER;
    if (i < n1) g_wq16[i] = __float2half(Wq[i]);
    int j = i - n1;
    if (j >= 0 && j < n2) g_wkv16[j] = __float2half(Wkv[j]);
    int k = j - n2;
    if (k >= 0 && k < INNER*DIM) g_wout16[k] = __float2half(Wout[k]);
}

// ---------------- fused layernorm (x and latents), writes fp16 ----------------
__global__ void __launch_bounds__(256) ln_kernel(
    const float* __restrict__ x, const float* __restrict__ lat,
    const float* __restrict__ gm, const float* __restrict__ bm,
    const float* __restrict__ gl, const float* __restrict__ bl)
{
    int r  = blockIdx.x;
    int b  = r / NKV;
    int jj = r - b * NKV;
    bool isl = (jj >= NMEDIA);
    const float* src = isl ? lat + ((size_t)b*NLAT + (jj - NMEDIA))*DIM
                           : x   + ((size_t)b*NMEDIA + jj)*DIM;
    const float* g  = isl ? gl : gm;
    const float* be = isl ? bl : bm;

    int t = threadIdx.x;
    float v[4];
    float s = 0.f, s2 = 0.f;
#pragma unroll
    for (int k = 0; k < 4; k++) {
        float u = src[t + 256*k];
        v[k] = u; s += u; s2 += u*u;
    }
#pragma unroll
    for (int o = 16; o; o >>= 1) {
        s  += __shfl_xor_sync(0xffffffffu, s,  o);
        s2 += __shfl_xor_sync(0xffffffffu, s2, o);
    }
    __shared__ float rs[8], rs2[8];
    if ((t & 31) == 0) { rs[t >> 5] = s; rs2[t >> 5] = s2; }
    __syncthreads();
    float ts = 0.f, ts2 = 0.f;
#pragma unroll
    for (int w = 0; w < 8; w++) { ts += rs[w]; ts2 += rs2[w]; }
    float mu  = ts * (1.f/DIM);
    float inv = rsqrtf(ts2 * (1.f/DIM) - mu*mu + 1e-5f);

    __half* d1 = g_kvin + (size_t)r * DIM;
    __half* d2 = isl ? g_lat16 + ((size_t)b*NLAT + (jj - NMEDIA))*DIM : nullptr;
#pragma unroll
    for (int k = 0; k < 4; k++) {
        int c = t + 256*k;
        __half hv = __float2half((v[k] - mu) * inv * g[c] + be[c]);
        d1[c] = hv;
        if (d2) d2[c] = hv;
    }
}

// ======== kv GEMM v6: R1 smem layout + 64x64 warp tile, 128 thr, 2 CTA/SM ========
// Same 128x128x32 block, sync LDG->STS single buffer; 4 warps, 1.5x less L1/MAC.
#define R1_BM 128
#define R1_BN 128
#define R1_BK 32

__global__ void __launch_bounds__(128, 2) gemm_kv_v6() {
    __shared__ __half As[R1_BM][R1_BK + 8];    // 128 x 40
    __shared__ __half Bs[R1_BK][R1_BN + 8];    // 32 x 136

    const int tid  = threadIdx.x;
    const int warp = tid >> 5, lane = tid & 31;
    const int wm = (warp & 1) * 64;
    const int wn = (warp >> 1) * 64;
    const int bm0 = blockIdx.y * R1_BM;
    const int bn0 = blockIdx.x * R1_BN;
    const int K = DIM, N = 2*INNER;

    float acc[4][8][4];
#pragma unroll
    for (int a = 0; a < 4; a++)
#pragma unroll
        for (int b = 0; b < 8; b++)
#pragma unroll
            for (int c = 0; c < 4; c++) acc[a][b][c] = 0.f;

    // A: 128 rows x 32 halves (64 B/row) -> each thread owns one row (4 uint4)
    // B: 32 rows x 128 halves (256 B/row) -> 4 threads/row, 64 B each
    const int brow = tid >> 2, bcol = (tid & 3) * 32;
    const __half* gA = g_kvin  + (size_t)(bm0 + tid) * K;
    const __half* gB = g_wkv16 + (size_t)brow * N + bn0 + bcol;

    for (int k0 = 0; k0 < K; k0 += R1_BK) {
        const __half* pa = gA + k0;
#pragma unroll
        for (int i = 0; i < 4; i++)
            *(uint4*)(&As[tid][i*8]) = *(const uint4*)(pa + i*8);
        const __half* pb = gB + (size_t)k0 * N;
#pragma unroll
        for (int i = 0; i < 4; i++)
            *(uint4*)(&Bs[brow][bcol + i*8]) = *(const uint4*)(pb + i*8);
        __syncthreads();

#pragma unroll
        for (int kc = 0; kc < R1_BK; kc += 16) {
            uint32_t af[4][4], bf[8][2];
#pragma unroll
            for (int mf = 0; mf < 4; mf++) {
                uint32_t ad = (uint32_t)__cvta_generic_to_shared(
                    &As[wm + mf*16 + (lane & 15)][kc + ((lane >> 4) << 3)]);
                asm volatile("ldmatrix.sync.aligned.m8n8.x4.shared.b16 {%0,%1,%2,%3}, [%4];"
                    : "=r"(af[mf][0]), "=r"(af[mf][1]), "=r"(af[mf][2]), "=r"(af[mf][3])
                    : "r"(ad) : "memory");
            }
            // B via x4.trans (R4-validated fragment order)
#pragma unroll
            for (int nq = 0; nq < 4; nq++) {
                uint32_t bd = (uint32_t)__cvta_generic_to_shared(
                    &Bs[kc + (lane & 15)][wn + nq*16 + ((lane >> 4) << 3)]);
                asm volatile("ldmatrix.sync.aligned.m8n8.x4.trans.shared.b16 {%0,%1,%2,%3}, [%4];"
                    : "=r"(bf[2*nq][0]), "=r"(bf[2*nq][1]),
                      "=r"(bf[2*nq+1][0]), "=r"(bf[2*nq+1][1])
                    : "r"(bd) : "memory");
            }
#pragma unroll
            for (int mf = 0; mf < 4; mf++)
#pragma unroll
                for (int nf = 0; nf < 8; nf++) {
                    asm volatile(
                        "mma.sync.aligned.m16n8k16.row.col.f32.f16.f16.f32 "
                        "{%0,%1,%2,%3}, {%4,%5,%6,%7}, {%8,%9}, {%0,%1,%2,%3};"
                        : "+f"(acc[mf][nf][0]), "+f"(acc[mf][nf][1]),
                          "+f"(acc[mf][nf][2]), "+f"(acc[mf][nf][3])
                        : "r"(af[mf][0]), "r"(af[mf][1]), "r"(af[mf][2]), "r"(af[mf][3]),
                          "r"(bf[nf][0]), "r"(bf[nf][1]));
                }
        }
        __syncthreads();
    }

    const int grp = lane >> 2, tig = lane & 3;
#pragma unroll
    for (int mf = 0; mf < 4; mf++)
#pragma unroll
        for (int nf = 0; nf < 8; nf++) {
            int row = bm0 + wm + mf*16 + grp;
            int col = bn0 + wn + nf*8 + tig*2;
            *(__half2*)&g_kv16[(size_t)row * N + col] =
                __floats2half2_rn(acc[mf][nf][0], acc[mf][nf][1]);
            *(__half2*)&g_kv16[(size_t)(row + 8) * N + col] =
                __floats2half2_rn(acc[mf][nf][2], acc[mf][nf][3]);
        }
}

// ---------------- double-buffered mma.sync GEMM (q and out GEMMs, small) ----------------
#define BM 128
#define BN 128
#define BKG 64
#define AS_STRIDE 72
#define BS_STRIDE 136
#define GEMM_SMEM ((2*BM*AS_STRIDE + 2*BKG*BS_STRIDE) * (int)sizeof(__half))

template<typename OutT>
__global__ void __launch_bounds__(256) gemm_db(
    const __half* __restrict__ A, const __half* __restrict__ Bmat,
    OutT* __restrict__ C, int M, int N, int K, float alpha)
{
    extern __shared__ __half smh[];
    __half* As = smh;
    __half* Bs = smh + 2*BM*AS_STRIDE;

    const int tid  = threadIdx.x;
    const int warp = tid >> 5, lane = tid & 31;
    const int wm = (warp & 1) * 64;
    const int wn = (warp >> 1) * 32;
    const int bm0 = blockIdx.y * BM;
    const int bn0 = blockIdx.x * BN;

    float acc[4][4][4];
#pragma unroll
    for (int a = 0; a < 4; a++)
#pragma unroll
        for (int b = 0; b < 4; b++)
#pragma unroll
            for (int c = 0; c < 4; c++) acc[a][b][c] = 0.f;

    const int arow = tid >> 1, acb = (tid & 1) * 32;
    const int brow = tid >> 2, bcb = (tid & 3) * 32;
    const uint32_t sA = (uint32_t)__cvta_generic_to_shared(As);
    const uint32_t sB = (uint32_t)__cvta_generic_to_shared(Bs);

    auto issue = [&](int k0, int st) {
        const __half* ga = A + (size_t)(bm0 + arow) * K + (k0 + acb);
        uint32_t da = sA + ((st*BM + arow)*AS_STRIDE + acb) * 2;
#pragma unroll
        for (int c = 0; c < 4; c++) cp_async16(da + c*16, ga + c*8);
        const __half* gb = Bmat + (size_t)(k0 + brow) * N + (bn0 + bcb);
        uint32_t db = sB + ((st*BKG + brow)*BS_STRIDE + bcb) * 2;
#pragma unroll
        for (int c = 0; c < 4; c++) cp_async16(db + c*16, gb + c*8);
    };

    issue(0, 0);
    cp_commit();

    int stage = 0;
    for (int k0 = 0; k0 < K; k0 += BKG) {
        if (k0 + BKG < K) { issue(k0 + BKG, stage ^ 1); cp_commit(); cp_wait1(); }
        else              { cp_wait0(); }
        __syncthreads();

        const __half* as = As + (size_t)stage * BM * AS_STRIDE;
        const __half* bs = Bs + (size_t)stage * BKG * BS_STRIDE;

#pragma unroll
        for (int kc = 0; kc < BKG; kc += 16) {
            uint32_t af[4][4], bf[4][2];
#pragma unroll
            for (int mf = 0; mf < 4; mf++) {
                uint32_t ad = (uint32_t)__cvta_generic_to_shared(
                    &as[(wm + mf*16 + (lane & 15))*AS_STRIDE + kc + ((lane >> 4) << 3)]);
                asm volatile("ldmatrix.sync.aligned.m8n8.x4.shared.b16 {%0,%1,%2,%3}, [%4];"
                    : "=r"(af[mf][0]), "=r"(af[mf][1]), "=r"(af[mf][2]), "=r"(af[mf][3])
                    : "r"(ad) : "memory");
            }
#pragma unroll
            for (int nf = 0; nf < 4; nf++) {
                uint32_t bd = (uint32_t)__cvta_generic_to_shared(
                    &bs[(kc + (lane & 15))*BS_STRIDE + wn + nf*8]);
                asm volatile("ldmatrix.sync.aligned.m8n8.x2.trans.shared.b16 {%0,%1}, [%2];"
                    : "=r"(bf[nf][0]), "=r"(bf[nf][1]) : "r"(bd) : "memory");
            }
#pragma unroll
            for (int mf = 0; mf < 4; mf++)
#pragma unroll
                for (int nf = 0; nf < 4; nf++) {
                    asm volatile(
                        "mma.sync.aligned.m16n8k16.row.col.f32.f16.f16.f32 "
                        "{%0,%1,%2,%3}, {%4,%5,%6,%7}, {%8,%9}, {%0,%1,%2,%3};"
                        : "+f"(acc[mf][nf][0]), "+f"(acc[mf][nf][1]),
                          "+f"(acc[mf][nf][2]), "+f"(acc[mf][nf][3])
                        : "r"(af[mf][0]), "r"(af[mf][1]), "r"(af[mf][2]), "r"(af[mf][3]),
                          "r"(bf[nf][0]), "r"(bf[nf][1]));
                }
        }
        __syncthreads();
        stage ^= 1;
    }

    const int grp = lane >> 2, tig = lane & 3;
#pragma unroll
    for (int mf = 0; mf < 4; mf++)
#pragma unroll
        for (int nf = 0; nf < 4; nf++) {
            int row = bm0 + wm + mf*16 + grp;
            int col = bn0 + wn + nf*8 + tig*2;
            if constexpr (sizeof(OutT) == 2) {
                *(__half2*)&C[(size_t)row * N + col] =
                    __floats2half2_rn(acc[mf][nf][0]*alpha, acc[mf][nf][1]*alpha);
                *(__half2*)&C[(size_t)(row + 8) * N + col] =
                    __floats2half2_rn(acc[mf][nf][2]*alpha, acc[mf][nf][3]*alpha);
            } else {
                *(float2*)&C[(size_t)row * N + col] =
                    make_float2(acc[mf][nf][0]*alpha, acc[mf][nf][1]*alpha);
                *(float2*)&C[(size_t)(row + 8) * N + col] =
                    make_float2(acc[mf][nf][2]*alpha, acc[mf][nf][3]*alpha);
            }
        }
}

// ---------------- tensor-core flash attention, split-KV ----------------
#define QS_STR 72

__global__ void __launch_bounds__(128) attn_mma_kernel() {
    __shared__ __half Qs[64][QS_STR];
    __shared__ __half Ks[2][64][QS_STR];
    __shared__ __half Vs[2][64][QS_STR];

    const int b = blockIdx.x, h = blockIdx.y, sp = blockIdx.z;
    const int tid = threadIdx.x;
    const int warp = tid >> 5, lane = tid & 31;
    const int grp = lane >> 2, tig = lane & 3;

    {
        int row = tid >> 1, cb = (tid & 1) * 32;
        const __half* q = g_q16 + ((size_t)(b*NLAT + row))*INNER + h*DHEAD + cb;
#pragma unroll
        for (int c = 0; c < 4; c++)
            *(uint4*)&Qs[row][cb + c*8] = *(const uint4*)(q + c*8);
    }
    __syncthreads();

    uint32_t qf[4][4];
#pragma unroll
    for (int kk = 0; kk < 4; kk++) {
        uint32_t ad = (uint32_t)__cvta_generic_to_shared(
            &Qs[warp*16 + (lane & 15)][kk*16 + ((lane >> 4) << 3)]);
        asm volatile("ldmatrix.sync.aligned.m8n8.x4.shared.b16 {%0,%1,%2,%3}, [%4];"
            : "=r"(qf[kk][0]), "=r"(qf[kk][1]), "=r"(qf[kk][2]), "=r"(qf[kk][3])
            : "r"(ad) : "memory");
    }

    const uint32_t sK = (uint32_t)__cvta_generic_to_shared(&Ks[0][0][0]);
    const uint32_t sV = (uint32_t)__cvta_generic_to_shared(&Vs[0][0][0]);
    const int ldr = tid >> 1, ldcb = (tid & 1) * 32;

    auto issue_kv = [&](int jt, int st) {
        size_t gbase = ((size_t)(b*NKV + jt*64 + ldr)) * (2*INNER) + h*DHEAD + ldcb;
        uint32_t dk = sK + ((st*64 + ldr)*QS_STR + ldcb) * 2;
        uint32_t dv = sV + ((st*64 + ldr)*QS_STR + ldcb) * 2;
#pragma unroll
        for (int c = 0; c < 4; c++) {
            cp_async16(dk + c*16, g_kv16 + gbase + c*8);
            cp_async16(dv + c*16, g_kv16 + gbase + INNER + c*8);
        }
    };

    const int t0 = sp * TILES_PER;
    issue_kv(t0, 0);
    cp_commit();

    float m0 = -1e30f, m1 = -1e30f, l0 = 0.f, l1 = 0.f;
    float of[8][4];
#pragma unroll
    for (int nf = 0; nf < 8; nf++)
#pragma unroll
        for (int c = 0; c < 4; c++) of[nf][c] = 0.f;

    int stage = 0;
    for (int jt = 0; jt < TILES_PER; jt++) {
        if (jt + 1 < TILES_PER) { issue_kv(t0 + jt + 1, stage ^ 1); cp_commit(); cp_wait1(); }
        else                    { cp_wait0(); }
        __syncthreads();

        float sf[8][4];
#pragma unroll
        for (int nf = 0; nf < 8; nf++) {
            sf[nf][0] = sf[nf][1] = sf[nf][2] = sf[nf][3] = 0.f;
#pragma unroll
            for (int kk = 0; kk < 4; kk++) {
                uint32_t bd = (uint32_t)__cvta_generic_to_shared(
                    &Ks[stage][nf*8 + (lane & 7)][kk*16 + ((lane >> 3) & 1) * 8]);
                uint32_t b0, b1;
                asm volatile("ldmatrix.sync.aligned.m8n8.x2.shared.b16 {%0,%1}, [%2];"
                    : "=r"(b0), "=r"(b1) : "r"(bd) : "memory");
                asm volatile(
                    "mma.sync.aligned.m16n8k16.row.col.f32.f16.f16.f32 "
                    "{%0,%1,%2,%3}, {%4,%5,%6,%7}, {%8,%9}, {%0,%1,%2,%3};"
                    : "+f"(sf[nf][0]), "+f"(sf[nf][1]), "+f"(sf[nf][2]), "+f"(sf[nf][3])
                    : "r"(qf[kk][0]), "r"(qf[kk][1]), "r"(qf[kk][2]), "r"(qf[kk][3]),
                      "r"(b0), "r"(b1));
            }
        }

        float mx0 = -1e30f, mx1 = -1e30f;
#pragma unroll
        for (int nf = 0; nf < 8; nf++) {
            mx0 = fmaxf(mx0, fmaxf(sf[nf][0], sf[nf][1]));
            mx1 = fmaxf(mx1, fmaxf(sf[nf][2], sf[nf][3]));
        }
        mx0 = fmaxf(mx0, __shfl_xor_sync(0xffffffffu, mx0, 1));
        mx0 = fmaxf(mx0, __shfl_xor_sync(0xffffffffu, mx0, 2));
        mx1 = fmaxf(mx1, __shfl_xor_sync(0xffffffffu, mx1, 1));
        mx1 = fmaxf(mx1, __shfl_xor_sync(0xffffffffu, mx1, 2));

        float mn0 = fmaxf(m0, mx0), mn1 = fmaxf(m1, mx1);
        float sc0 = __expf(m0 - mn0), sc1 = __expf(m1 - mn1);

        uint32_t pa[8], pb[8];
        float ls0 = 0.f, ls1 = 0.f;
#pragma unroll
        for (int nf = 0; nf < 8; nf++) {
            float p0 = __expf(sf[nf][0] - mn0);
            float p1 = __expf(sf[nf][1] - mn0);
            float p2 = __expf(sf[nf][2] - mn1);
            float p3 = __expf(sf[nf][3] - mn1);
            ls0 += p0 + p1; ls1 += p2 + p3;
            __half2 ha = __floats2half2_rn(p0, p1);
            __half2 hb = __floats2half2_rn(p2, p3);
            pa[nf] = *(uint32_t*)&ha;
            pb[nf] = *(uint32_t*)&hb;
        }
        ls0 += __shfl_xor_sync(0xffffffffu, ls0, 1);
        ls0 += __shfl_xor_sync(0xffffffffu, ls0, 2);
        ls1 += __shfl_xor_sync(0xffffffffu, ls1, 1);
        ls1 += __shfl_xor_sync(0xffffffffu, ls1, 2);

        l0 = l0 * sc0 + ls0;
        l1 = l1 * sc1 + ls1;
        m0 = mn0; m1 = mn1;
#pragma unroll
        for (int nf = 0; nf < 8; nf++) {
            of[nf][0] *= sc0; of[nf][1] *= sc0;
            of[nf][2] *= sc1; of[nf][3] *= sc1;
        }

#pragma unroll
        for (int nf = 0; nf < 8; nf++) {
#pragma unroll
            for (int kk = 0; kk < 4; kk++) {
                uint32_t bd = (uint32_t)__cvta_generic_to_shared(
                    &Vs[stage][kk*16 + (lane & 15)][nf*8]);
                uint32_t b0, b1;
                asm volatile("ldmatrix.sync.aligned.m8n8.x2.trans.shared.b16 {%0,%1}, [%2];"
                    : "=r"(b0), "=r"(b1) : "r"(bd) : "memory");
                asm volatile(
                    "mma.sync.aligned.m16n8k16.row.col.f32.f16.f16.f32 "
                    "{%0,%1,%2,%3}, {%4,%5,%6,%7}, {%8,%9}, {%0,%1,%2,%3};"
                    : "+f"(of[nf][0]), "+f"(of[nf][1]), "+f"(of[nf][2]), "+f"(of[nf][3])
                    : "r"(pa[2*kk]), "r"(pb[2*kk]), "r"(pa[2*kk+1]), "r"(pb[2*kk+1]),
                      "r"(b0), "r"(b1));
            }
        }
        __syncthreads();
        stage ^= 1;
    }

    const int row0g = b*NLAT + warp*16 + grp;
    float* op0 = g_opart + ((size_t)sp*NB*NLAT + row0g)*INNER + h*DHEAD;
    float* op1 = op0 + (size_t)8*INNER;
#pragma unroll
    for (int nf = 0; nf < 8; nf++) {
        int col = nf*8 + tig*2;
        *(float2*)&op0[col] = make_float2(of[nf][0], of[nf][1]);
        *(float2*)&op1[col] = make_float2(of[nf][2], of[nf][3]);
    }
    if (tig == 0) {
        size_t i0 = (((size_t)sp*NB*NLAT + row0g)*NHEADS + h)*2;
        g_mlp[i0]   = m0; g_mlp[i0+1] = l0;
        size_t i1 = (((size_t)sp*NB*NLAT + row0g + 8)*NHEADS + h)*2;
        g_mlp[i1]   = m1; g_mlp[i1+1] = l1;
    }
}

// ---------------- split-KV combine ----------------
__global__ void __launch_bounds__(256) attn_combine() {
    int idx = blockIdx.x * 256 + threadIdx.x;
    int row = idx >> 9;
    int c2  = (idx & 511) * 2;
    int h   = c2 >> 6;

    float ms[SPLIT], ls[SPLIT];
    float M = -1e30f;
#pragma unroll
    for (int s = 0; s < SPLIT; s++) {
        size_t i = (((size_t)s*NB*NLAT + row)*NHEADS + h)*2;
        ms[s] = g_mlp[i]; ls[s] = g_mlp[i+1];
        M = fmaxf(M, ms[s]);
    }
    float L = 0.f, o0 = 0.f, o1 = 0.f;
#pragma unroll
    for (int s = 0; s < SPLIT; s++) {
        float w = __expf(ms[s] - M);
        L += ls[s] * w;
        float2 v = *(const float2*)&g_opart[((size_t)s*NB*NLAT + row)*INNER + c2];
        o0 += v.x * w; o1 += v.y * w;
    }
    float inv = 1.f / L;
    *(__half2*)&g_ao16[(size_t)row*INNER + c2] = __floats2half2_rn(o0*inv, o1*inv);
}

// ---------------- launch ----------------
extern "C" void kernel_launch(void* const* d_in, const int* in_sizes, int n_in,
                              void* d_out, int out_size) {
    const float* x    = (const float*)d_in[0];
    const float* lat  = (const float*)d_in[1];
    const float* gm   = (const float*)d_in[2];
    const float* bm   = (const float*)d_in[3];
    const float* gl   = (const float*)d_in[4];
    const float* bl   = (const float*)d_in[5];
    const float* Wq   = (const float*)d_in[6];
    const float* Wkv  = (const float*)d_in[7];
    const float* Wout = (const float*)d_in[8];
    float* out = (float*)d_out;

    void *p_lat, *p_q, *p_ao, *p_wq, *p_wout;
    cudaGetSymbolAddress(&p_lat,  g_lat16);
    cudaGetSymbolAddress(&p_q,    g_q16);
    cudaGetSymbolAddress(&p_ao,   g_ao16);
    cudaGetSymbolAddress(&p_wq,   g_wq16);
    cudaGetSymbolAddress(&p_wout, g_wout16);

    cudaFuncSetAttribute(gemm_db<__half>, cudaFuncAttributeMaxDynamicSharedMemorySize, GEMM_SMEM);
    cudaFuncSetAttribute(gemm_db<float>,  cudaFuncAttributeMaxDynamicSharedMemorySize, GEMM_SMEM);

    // 1. weights fp32 -> fp16
    cvt_weights<<<(4*1024*1024 + 255)/256, 256>>>(Wq, Wkv, Wout);

    // 2. layernorm
    ln_kernel<<<NB*NKV, 256>>>(x, lat, gm, bm, gl, bl);

    // 3. q = lat_ln @ Wq * d^-0.5
    {
        dim3 grid(INNER/BN, (NB*NLAT)/BM);
        gemm_db<__half><<<grid, 256, GEMM_SMEM>>>((const __half*)p_lat, (const __half*)p_wq,
                                                  (__half*)p_q, NB*NLAT, INNER, DIM, 0.125f);
    }

    // 4. kv GEMM — R1 layout, 64x64 warp tile, 128 threads, 2 CTA/SM
    {
        dim3 grid((2*INNER)/R1_BN, (NB*NKV)/R1_BM);   // (16, 520)
        gemm_kv_v6<<<grid, 128>>>();
    }

    // 5. attention (split-KV) + combine
    {
        dim3 grid(NB, NHEADS, SPLIT);
        attn_mma_kernel<<<grid, 128>>>();
        attn_combine<<<(NB*NLAT*INNER/2 + 255)/256, 256>>>();
    }

    // 6. out = ao @ Wout -> d_out (fp32)
    {
        dim3 grid(DIM/BN, (NB*NLAT)/BM);
        gemm_db<float><<<grid, 256, GEMM_SMEM>>>((const __half*)p_ao, (const __half*)p_wout,
                                                 out, NB*NLAT, DIM, INNER, 1.0f);
    }
}

// round 16
// speedup vs baseline: 1.2810x; 1.2810x over previous
#include <cuda_runtime.h>
#include <cuda_fp16.h>
#include <cstdint>

#define NB     16
#define NMEDIA 4096
#define NLAT   64
#define NKV    4160
#define DIM    1024
#define INNER  1024
#define NHEADS 16
#define DHEAD  64
#define SPLIT  5
#define TILES_PER 13   // 65 K-tiles of 64 / SPLIT

// ---------------- scratch (static device globals; no runtime allocation) ----------------
__device__ __half g_kvin [(size_t)NB*NKV*DIM];
__device__ __half g_lat16[(size_t)NB*NLAT*DIM];
__device__ __half g_q16  [(size_t)NB*NLAT*INNER];
__device__ __half g_kv16 [(size_t)NB*NKV*2*INNER];
__device__ __half g_ao16 [(size_t)NB*NLAT*INNER];
__device__ __half g_wq16 [(size_t)DIM*INNER];
__device__ __half g_wkv16[(size_t)DIM*2*INNER];    // Wkv fp16 [K][N]
__device__ __half g_wout16[(size_t)INNER*DIM];
__device__ float  g_opart[(size_t)SPLIT*NB*NLAT*INNER];
__device__ float  g_mlp  [(size_t)SPLIT*NB*NLAT*NHEADS*2];

// ---------------- helpers ----------------
__device__ __forceinline__ void cp_async16(uint32_t smem_dst, const void* gsrc) {
    asm volatile("cp.async.cg.shared.global [%0], [%1], 16;\n" :: "r"(smem_dst), "l"(gsrc));
}
__device__ __forceinline__ void cp_commit() { asm volatile("cp.async.commit_group;\n" ::); }
__device__ __forceinline__ void cp_wait1()  { asm volatile("cp.async.wait_group 1;\n" ::: "memory"); }
__device__ __forceinline__ void cp_wait0()  { asm volatile("cp.async.wait_group 0;\n" ::: "memory"); }

// ---------------- weight conversion fp32 -> fp16 ----------------
__global__ void cvt_weights(const float* __restrict__ Wq,
                            const float* __restrict__ Wkv,
                            const float* __restrict__ Wout) {
    int i = blockIdx.x * blockDim.x + threadIdx.x;
    const int n1 = DIM*INNER;
    const int n2 = DIM*2*INNER;
    if (i < n1) g_wq16[i] = __float2half(Wq[i]);
    int j = i - n1;
    if (j >= 0 && j < n2) g_wkv16[j] = __float2half(Wkv[j]);
    int k = j - n2;
    if (k >= 0 && k < INNER*DIM) g_wout16[k] = __float2half(Wout[k]);
}

// ---------------- fused layernorm (x and latents), writes fp16 ----------------
__global__ void __launch_bounds__(256) ln_kernel(
    const float* __restrict__ x, const float* __restrict__ lat,
    const float* __restrict__ gm, const float* __restrict__ bm,
    const float* __restrict__ gl, const float* __restrict__ bl)
{
    int r  = blockIdx.x;
    int b  = r / NKV;
    int jj = r - b * NKV;
    bool isl = (jj >= NMEDIA);
    const float* src = isl ? lat + ((size_t)b*NLAT + (jj - NMEDIA))*DIM
                           : x   + ((size_t)b*NMEDIA + jj)*DIM;
    const float* g  = isl ? gl : gm;
    const float* be = isl ? bl : bm;

    int t = threadIdx.x;
    float v[4];
    float s = 0.f, s2 = 0.f;
#pragma unroll
    for (int k = 0; k < 4; k++) {
        float u = src[t + 256*k];
        v[k] = u; s += u; s2 += u*u;
    }
#pragma unroll
    for (int o = 16; o; o >>= 1) {
        s  += __shfl_xor_sync(0xffffffffu, s,  o);
        s2 += __shfl_xor_sync(0xffffffffu, s2, o);
    }
    __shared__ float rs[8], rs2[8];
    if ((t & 31) == 0) { rs[t >> 5] = s; rs2[t >> 5] = s2; }
    __syncthreads();
    float ts = 0.f, ts2 = 0.f;
#pragma unroll
    for (int w = 0; w < 8; w++) { ts += rs[w]; ts2 += rs2[w]; }
    float mu  = ts * (1.f/DIM);
    float inv = rsqrtf(ts2 * (1.f/DIM) - mu*mu + 1e-5f);

    __half* d1 = g_kvin + (size_t)r * DIM;
    __half* d2 = isl ? g_lat16 + ((size_t)b*NLAT + (jj - NMEDIA))*DIM : nullptr;
#pragma unroll
    for (int k = 0; k < 4; k++) {
        int c = t + 256*k;
        __half hv = __float2half((v[k] - mu) * inv * g[c] + be[c]);
        d1[c] = hv;
        if (d2) d2[c] = hv;
    }
}

// ======== kv GEMM (R1/R13 design — empirical best: 969 µs @ tensor 47.3%) ========
// Sync LDG.128->STS.128, single-buffered smem, 128x128x32, 2 CTAs/SM, 8 warps.
#define R1_BM 128
#define R1_BN 128
#define R1_BK 32

__global__ void __launch_bounds__(256, 2) gemm_kv_r1() {
    __shared__ __half As[R1_BM][R1_BK + 8];    // 128 x 40
    __shared__ __half Bs[R1_BK][R1_BN + 8];    // 32 x 136

    const int tid  = threadIdx.x;
    const int warp = tid >> 5, lane = tid & 31;
    const int wm = (warp & 1) * 64;
    const int wn = (warp >> 1) * 32;
    const int bm0 = blockIdx.y * R1_BM;
    const int bn0 = blockIdx.x * R1_BN;
    const int K = DIM, N = 2*INNER;

    float acc[4][4][4];
#pragma unroll
    for (int a = 0; a < 4; a++)
#pragma unroll
        for (int b = 0; b < 4; b++)
#pragma unroll
            for (int c = 0; c < 4; c++) acc[a][b][c] = 0.f;

    const int arow = tid >> 2, acol = (tid & 3) * 8;    // A tile: 128 x 32
    const int brow = tid >> 4, bcol = (tid & 15) * 8;   // B tile: 32 x 128

    for (int k0 = 0; k0 < K; k0 += R1_BK) {
        const __half* ga = g_kvin + (size_t)(bm0 + arow) * K + (k0 + acol);
        *(uint4*)(&As[arow     ][acol]) = *(const uint4*)ga;
        *(uint4*)(&As[arow + 64][acol]) = *(const uint4*)(ga + (size_t)64 * K);
        const __half* gb = g_wkv16 + (size_t)(k0 + brow) * N + (bn0 + bcol);
        *(uint4*)(&Bs[brow     ][bcol]) = *(const uint4*)gb;
        *(uint4*)(&Bs[brow + 16][bcol]) = *(const uint4*)(gb + (size_t)16 * N);
        __syncthreads();

#pragma unroll
        for (int kc = 0; kc < R1_BK; kc += 16) {
            uint32_t af[4][4], bf[4][2];
#pragma unroll
            for (int mf = 0; mf < 4; mf++) {
                uint32_t ad = (uint32_t)__cvta_generic_to_shared(
                    &As[wm + mf*16 + (lane & 15)][kc + ((lane >> 4) << 3)]);
                asm volatile("ldmatrix.sync.aligned.m8n8.x4.shared.b16 {%0,%1,%2,%3}, [%4];"
                    : "=r"(af[mf][0]), "=r"(af[mf][1]), "=r"(af[mf][2]), "=r"(af[mf][3])
                    : "r"(ad) : "memory");
            }
#pragma unroll
            for (int nf = 0; nf < 4; nf++) {
                uint32_t bd = (uint32_t)__cvta_generic_to_shared(
                    &Bs[kc + (lane & 15)][wn + nf*8]);
                asm volatile("ldmatrix.sync.aligned.m8n8.x2.trans.shared.b16 {%0,%1}, [%2];"
                    : "=r"(bf[nf][0]), "=r"(bf[nf][1]) : "r"(bd) : "memory");
            }
#pragma unroll
            for (int mf = 0; mf < 4; mf++)
#pragma unroll
                for (int nf = 0; nf < 4; nf++) {
                    asm volatile(
                        "mma.sync.aligned.m16n8k16.row.col.f32.f16.f16.f32 "
                        "{%0,%1,%2,%3}, {%4,%5,%6,%7}, {%8,%9}, {%0,%1,%2,%3};"
                        : "+f"(acc[mf][nf][0]), "+f"(acc[mf][nf][1]),
                          "+f"(acc[mf][nf][2]), "+f"(acc[mf][nf][3])
                        : "r"(af[mf][0]), "r"(af[mf][1]), "r"(af[mf][2]), "r"(af[mf][3]),
                          "r"(bf[nf][0]), "r"(bf[nf][1]));
                }
        }
        __syncthreads();
    }

    const int grp = lane >> 2, tig = lane & 3;
#pragma unroll
    for (int mf = 0; mf < 4; mf++)
#pragma unroll
        for (int nf = 0; nf < 4; nf++) {
            int row = bm0 + wm + mf*16 + grp;
            int col = bn0 + wn + nf*8 + tig*2;
            *(__half2*)&g_kv16[(size_t)row * N + col] =
                __floats2half2_rn(acc[mf][nf][0], acc[mf][nf][1]);
            *(__half2*)&g_kv16[(size_t)(row + 8) * N + col] =
                __floats2half2_rn(acc[mf][nf][2], acc[mf][nf][3]);
        }
}

// ---------------- double-buffered mma.sync GEMM (q and out GEMMs, small) ----------------
#define BM 128
#define BN 128
#define BKG 64
#define AS_STRIDE 72
#define BS_STRIDE 136
#define GEMM_SMEM ((2*BM*AS_STRIDE + 2*BKG*BS_STRIDE) * (int)sizeof(__half))

template<typename OutT>
__global__ void __launch_bounds__(256) gemm_db(
    const __half* __restrict__ A, const __half* __restrict__ Bmat,
    OutT* __restrict__ C, int M, int N, int K, float alpha)
{
    extern __shared__ __half smh[];
    __half* As = smh;
    __half* Bs = smh + 2*BM*AS_STRIDE;

    const int tid  = threadIdx.x;
    const int warp = tid >> 5, lane = tid & 31;
    const int wm = (warp & 1) * 64;
    const int wn = (warp >> 1) * 32;
    const int bm0 = blockIdx.y * BM;
    const int bn0 = blockIdx.x * BN;

    float acc[4][4][4];
#pragma unroll
    for (int a = 0; a < 4; a++)
#pragma unroll
        for (int b = 0; b < 4; b++)
#pragma unroll
            for (int c = 0; c < 4; c++) acc[a][b][c] = 0.f;

    const int arow = tid >> 1, acb = (tid & 1) * 32;
    const int brow = tid >> 2, bcb = (tid & 3) * 32;
    const uint32_t sA = (uint32_t)__cvta_generic_to_shared(As);
    const uint32_t sB = (uint32_t)__cvta_generic_to_shared(Bs);

    auto issue = [&](int k0, int st) {
        const __half* ga = A + (size_t)(bm0 + arow) * K + (k0 + acb);
        uint32_t da = sA + ((st*BM + arow)*AS_STRIDE + acb) * 2;
#pragma unroll
        for (int c = 0; c < 4; c++) cp_async16(da + c*16, ga + c*8);
        const __half* gb = Bmat + (size_t)(k0 + brow) * N + (bn0 + bcb);
        uint32_t db = sB + ((st*BKG + brow)*BS_STRIDE + bcb) * 2;
#pragma unroll
        for (int c = 0; c < 4; c++) cp_async16(db + c*16, gb + c*8);
    };

    issue(0, 0);
    cp_commit();

    int stage = 0;
    for (int k0 = 0; k0 < K; k0 += BKG) {
        if (k0 + BKG < K) { issue(k0 + BKG, stage ^ 1); cp_commit(); cp_wait1(); }
        else              { cp_wait0(); }
        __syncthreads();

        const __half* as = As + (size_t)stage * BM * AS_STRIDE;
        const __half* bs = Bs + (size_t)stage * BKG * BS_STRIDE;

#pragma unroll
        for (int kc = 0; kc < BKG; kc += 16) {
            uint32_t af[4][4], bf[4][2];
#pragma unroll
            for (int mf = 0; mf < 4; mf++) {
                uint32_t ad = (uint32_t)__cvta_generic_to_shared(
                    &as[(wm + mf*16 + (lane & 15))*AS_STRIDE + kc + ((lane >> 4) << 3)]);
                asm volatile("ldmatrix.sync.aligned.m8n8.x4.shared.b16 {%0,%1,%2,%3}, [%4];"
                    : "=r"(af[mf][0]), "=r"(af[mf][1]), "=r"(af[mf][2]), "=r"(af[mf][3])
                    : "r"(ad) : "memory");
            }
#pragma unroll
            for (int nf = 0; nf < 4; nf++) {
                uint32_t bd = (uint32_t)__cvta_generic_to_shared(
                    &bs[(kc + (lane & 15))*BS_STRIDE + wn + nf*8]);
                asm volatile("ldmatrix.sync.aligned.m8n8.x2.trans.shared.b16 {%0,%1}, [%2];"
                    : "=r"(bf[nf][0]), "=r"(bf[nf][1]) : "r"(bd) : "memory");
            }
#pragma unroll
            for (int mf = 0; mf < 4; mf++)
#pragma unroll
                for (int nf = 0; nf < 4; nf++) {
                    asm volatile(
                        "mma.sync.aligned.m16n8k16.row.col.f32.f16.f16.f32 "
                        "{%0,%1,%2,%3}, {%4,%5,%6,%7}, {%8,%9}, {%0,%1,%2,%3};"
                        : "+f"(acc[mf][nf][0]), "+f"(acc[mf][nf][1]),
                          "+f"(acc[mf][nf][2]), "+f"(acc[mf][nf][3])
                        : "r"(af[mf][0]), "r"(af[mf][1]), "r"(af[mf][2]), "r"(af[mf][3]),
                          "r"(bf[nf][0]), "r"(bf[nf][1]));
                }
        }
        __syncthreads();
        stage ^= 1;
    }

    const int grp = lane >> 2, tig = lane & 3;
#pragma unroll
    for (int mf = 0; mf < 4; mf++)
#pragma unroll
        for (int nf = 0; nf < 4; nf++) {
            int row = bm0 + wm + mf*16 + grp;
            int col = bn0 + wn + nf*8 + tig*2;
            if constexpr (sizeof(OutT) == 2) {
                *(__half2*)&C[(size_t)row * N + col] =
                    __floats2half2_rn(acc[mf][nf][0]*alpha, acc[mf][nf][1]*alpha);
                *(__half2*)&C[(size_t)(row + 8) * N + col] =
                    __floats2half2_rn(acc[mf][nf][2]*alpha, acc[mf][nf][3]*alpha);
            } else {
                *(float2*)&C[(size_t)row * N + col] =
                    make_float2(acc[mf][nf][0]*alpha, acc[mf][nf][1]*alpha);
                *(float2*)&C[(size_t)(row + 8) * N + col] =
                    make_float2(acc[mf][nf][2]*alpha, acc[mf][nf][3]*alpha);
            }
        }
}

// ---------------- tensor-core flash attention, split-KV (fp16x2 ex2 softmax) ----------------
#define QS_STR 72

__global__ void __launch_bounds__(128) attn_mma_kernel() {
    __shared__ __half Qs[64][QS_STR];
    __shared__ __half Ks[2][64][QS_STR];
    __shared__ __half Vs[2][64][QS_STR];

    const int b = blockIdx.x, h = blockIdx.y, sp = blockIdx.z;
    const int tid = threadIdx.x;
    const int warp = tid >> 5, lane = tid & 31;
    const int grp = lane >> 2, tig = lane & 3;

    {
        int row = tid >> 1, cb = (tid & 1) * 32;
        const __half* q = g_q16 + ((size_t)(b*NLAT + row))*INNER + h*DHEAD + cb;
#pragma unroll
        for (int c = 0; c < 4; c++)
            *(uint4*)&Qs[row][cb + c*8] = *(const uint4*)(q + c*8);
    }
    __syncthreads();

    uint32_t qf[4][4];
#pragma unroll
    for (int kk = 0; kk < 4; kk++) {
        uint32_t ad = (uint32_t)__cvta_generic_to_shared(
            &Qs[warp*16 + (lane & 15)][kk*16 + ((lane >> 4) << 3)]);
        asm volatile("ldmatrix.sync.aligned.m8n8.x4.shared.b16 {%0,%1,%2,%3}, [%4];"
            : "=r"(qf[kk][0]), "=r"(qf[kk][1]), "=r"(qf[kk][2]), "=r"(qf[kk][3])
            : "r"(ad) : "memory");
    }

    const uint32_t sK = (uint32_t)__cvta_generic_to_shared(&Ks[0][0][0]);
    const uint32_t sV = (uint32_t)__cvta_generic_to_shared(&Vs[0][0][0]);
    const int ldr = tid >> 1, ldcb = (tid & 1) * 32;

    auto issue_kv = [&](int jt, int st) {
        size_t gbase = ((size_t)(b*NKV + jt*64 + ldr)) * (2*INNER) + h*DHEAD + ldcb;
        uint32_t dk = sK + ((st*64 + ldr)*QS_STR + ldcb) * 2;
        uint32_t dv = sV + ((st*64 + ldr)*QS_STR + ldcb) * 2;
#pragma unroll
        for (int c = 0; c < 4; c++) {
            cp_async16(dk + c*16, g_kv16 + gbase + c*8);
            cp_async16(dv + c*16, g_kv16 + gbase + INNER + c*8);
        }
    };

    const int t0 = sp * TILES_PER;
    issue_kv(t0, 0);
    cp_commit();

    float m0 = -1e30f, m1 = -1e30f, l0 = 0.f, l1 = 0.f;
    float of[8][4];
#pragma unroll
    for (int nf = 0; nf < 8; nf++)
#pragma unroll
        for (int c = 0; c < 4; c++) of[nf][c] = 0.f;

    const float L2E = 1.4426950408889634f;

    int stage = 0;
    for (int jt = 0; jt < TILES_PER; jt++) {
        if (jt + 1 < TILES_PER) { issue_kv(t0 + jt + 1, stage ^ 1); cp_commit(); cp_wait1(); }
        else                    { cp_wait0(); }
        __syncthreads();

        float sf[8][4];
#pragma unroll
        for (int nf = 0; nf < 8; nf++) {
            sf[nf][0] = sf[nf][1] = sf[nf][2] = sf[nf][3] = 0.f;
#pragma unroll
            for (int kk = 0; kk < 4; kk++) {
                uint32_t bd = (uint32_t)__cvta_generic_to_shared(
                    &Ks[stage][nf*8 + (lane & 7)][kk*16 + ((lane >> 3) & 1) * 8]);
                uint32_t b0, b1;
                asm volatile("ldmatrix.sync.aligned.m8n8.x2.shared.b16 {%0,%1}, [%2];"
                    : "=r"(b0), "=r"(b1) : "r"(bd) : "memory");
                asm volatile(
                    "mma.sync.aligned.m16n8k16.row.col.f32.f16.f16.f32 "
                    "{%0,%1,%2,%3}, {%4,%5,%6,%7}, {%8,%9}, {%0,%1,%2,%3};"
                    : "+f"(sf[nf][0]), "+f"(sf[nf][1]), "+f"(sf[nf][2]), "+f"(sf[nf][3])
                    : "r"(qf[kk][0]), "r"(qf[kk][1]), "r"(qf[kk][2]), "r"(qf[kk][3]),
                      "r"(b0), "r"(b1));
            }
        }

        float mx0 = -1e30f, mx1 = -1e30f;
#pragma unroll
        for (int nf = 0; nf < 8; nf++) {
            mx0 = fmaxf(mx0, fmaxf(sf[nf][0], sf[nf][1]));
            mx1 = fmaxf(mx1, fmaxf(sf[nf][2], sf[nf][3]));
        }
        mx0 = fmaxf(mx0, __shfl_xor_sync(0xffffffffu, mx0, 1));
        mx0 = fmaxf(mx0, __shfl_xor_sync(0xffffffffu, mx0, 2));
        mx1 = fmaxf(mx1, __shfl_xor_sync(0xffffffffu, mx1, 1));
        mx1 = fmaxf(mx1, __shfl_xor_sync(0xffffffffu, mx1, 2));

        float mn0 = fmaxf(m0, mx0), mn1 = fmaxf(m1, mx1);
        float sc0 = __expf(m0 - mn0), sc1 = __expf(m1 - mn1);

        // ---- exp via ex2.approx.f16x2: half the MUFU ops; P is fp16 for the mma anyway ----
        uint32_t pa[8], pb[8];
        float ls0 = 0.f, ls1 = 0.f;
#pragma unroll
        for (int nf = 0; nf < 8; nf++) {
            __half2 ta = __floats2half2_rn((sf[nf][0] - mn0) * L2E, (sf[nf][1] - mn0) * L2E);
            __half2 tb = __floats2half2_rn((sf[nf][2] - mn1) * L2E, (sf[nf][3] - mn1) * L2E);
            uint32_t ua = *(uint32_t*)&ta, ub = *(uint32_t*)&tb;
            uint32_t ra, rb;
            asm("ex2.approx.f16x2 %0, %1;" : "=r"(ra) : "r"(ua));
            asm("ex2.approx.f16x2 %0, %1;" : "=r"(rb) : "r"(ub));
            pa[nf] = ra; pb[nf] = rb;
            float2 fa = __half22float2(*(__half2*)&ra);
            float2 fb = __half22float2(*(__half2*)&rb);
            ls0 += fa.x + fa.y;
            ls1 += fb.x + fb.y;
        }
        ls0 += __shfl_xor_sync(0xffffffffu, ls0, 1);
        ls0 += __shfl_xor_sync(0xffffffffu, ls0, 2);
        ls1 += __shfl_xor_sync(0xffffffffu, ls1, 1);
        ls1 += __shfl_xor_sync(0xffffffffu, ls1, 2);

        l0 = l0 * sc0 + ls0;
        l1 = l1 * sc1 + ls1;
        m0 = mn0; m1 = mn1;
#pragma unroll
        for (int nf = 0; nf < 8; nf++) {
            of[nf][0] *= sc0; of[nf][1] *= sc0;
            of[nf][2] *= sc1; of[nf][3] *= sc1;
        }

#pragma unroll
        for (int nf = 0; nf < 8; nf++) {
#pragma unroll
            for (int kk = 0; kk < 4; kk++) {
                uint32_t bd = (uint32_t)__cvta_generic_to_shared(
                    &Vs[stage][kk*16 + (lane & 15)][nf*8]);
                uint32_t b0, b1;
                asm volatile("ldmatrix.sync.aligned.m8n8.x2.trans.shared.b16 {%0,%1}, [%2];"
                    : "=r"(b0), "=r"(b1) : "r"(bd) : "memory");
                asm volatile(
                    "mma.sync.aligned.m16n8k16.row.col.f32.f16.f16.f32 "
                    "{%0,%1,%2,%3}, {%4,%5,%6,%7}, {%8,%9}, {%0,%1,%2,%3};"
                    : "+f"(of[nf][0]), "+f"(of[nf][1]), "+f"(of[nf][2]), "+f"(of[nf][3])
                    : "r"(pa[2*kk]), "r"(pb[2*kk]), "r"(pa[2*kk+1]), "r"(pb[2*kk+1]),
                      "r"(b0), "r"(b1));
            }
        }
        __syncthreads();
        stage ^= 1;
    }

    const int row0g = b*NLAT + warp*16 + grp;
    float* op0 = g_opart + ((size_t)sp*NB*NLAT + row0g)*INNER + h*DHEAD;
    float* op1 = op0 + (size_t)8*INNER;
#pragma unroll
    for (int nf = 0; nf < 8; nf++) {
        int col = nf*8 + tig*2;
        *(float2*)&op0[col] = make_float2(of[nf][0], of[nf][1]);
        *(float2*)&op1[col] = make_float2(of[nf][2], of[nf][3]);
    }
    if (tig == 0) {
        size_t i0 = (((size_t)sp*NB*NLAT + row0g)*NHEADS + h)*2;
        g_mlp[i0]   = m0; g_mlp[i0+1] = l0;
        size_t i1 = (((size_t)sp*NB*NLAT + row0g + 8)*NHEADS + h)*2;
        g_mlp[i1]   = m1; g_mlp[i1+1] = l1;
    }
}

// ---------------- split-KV combine ----------------
__global__ void __launch_bounds__(256) attn_combine() {
    int idx = blockIdx.x * 256 + threadIdx.x;
    int row = idx >> 9;
    int c2  = (idx & 511) * 2;
    int h   = c2 >> 6;

    float ms[SPLIT], ls[SPLIT];
    float M = -1e30f;
#pragma unroll
    for (int s = 0; s < SPLIT; s++) {
        size_t i = (((size_t)s*NB*NLAT + row)*NHEADS + h)*2;
        ms[s] = g_mlp[i]; ls[s] = g_mlp[i+1];
        M = fmaxf(M, ms[s]);
    }
    float L = 0.f, o0 = 0.f, o1 = 0.f;
#pragma unroll
    for (int s = 0; s < SPLIT; s++) {
        float w = __expf(ms[s] - M);
        L += ls[s] * w;
        float2 v = *(const float2*)&g_opart[((size_t)s*NB*NLAT + row)*INNER + c2];
        o0 += v.x * w; o1 += v.y * w;
    }
    float inv = 1.f / L;
    *(__half2*)&g_ao16[(size_t)row*INNER + c2] = __floats2half2_rn(o0*inv, o1*inv);
}

// ---------------- launch ----------------
extern "C" void kernel_launch(void* const* d_in, const int* in_sizes, int n_in,
                              void* d_out, int out_size) {
    const float* x    = (const float*)d_in[0];
    const float* lat  = (const float*)d_in[1];
    const float* gm   = (const float*)d_in[2];
    const float* bm   = (const float*)d_in[3];
    const float* gl   = (const float*)d_in[4];
    const float* bl   = (const float*)d_in[5];
    const float* Wq   = (const float*)d_in[6];
    const float* Wkv  = (const float*)d_in[7];
    const float* Wout = (const float*)d_in[8];
    float* out = (float*)d_out;

    void *p_lat, *p_q, *p_ao, *p_wq, *p_wout;
    cudaGetSymbolAddress(&p_lat,  g_lat16);
    cudaGetSymbolAddress(&p_q,    g_q16);
    cudaGetSymbolAddress(&p_ao,   g_ao16);
    cudaGetSymbolAddress(&p_wq,   g_wq16);
    cudaGetSymbolAddress(&p_wout, g_wout16);

    cudaFuncSetAttribute(gemm_db<__half>, cudaFuncAttributeMaxDynamicSharedMemorySize, GEMM_SMEM);
    cudaFuncSetAttribute(gemm_db<float>,  cudaFuncAttributeMaxDynamicSharedMemorySize, GEMM_SMEM);

    // 1. weights fp32 -> fp16
    cvt_weights<<<(4*1024*1024 + 255)/256, 256>>>(Wq, Wkv, Wout);

    // 2. layernorm
    ln_kernel<<<NB*NKV, 256>>>(x, lat, gm, bm, gl, bl);

    // 3. q = lat_ln @ Wq * d^-0.5
    {
        dim3 grid(INNER/BN, (NB*NLAT)/BM);
        gemm_db<__half><<<grid, 256, GEMM_SMEM>>>((const __half*)p_lat, (const __half*)p_wq,
                                                  (__half*)p_q, NB*NLAT, INNER, DIM, 0.125f);
    }

    // 4. kv GEMM — R13 empirical-best design (unchanged)
    {
        dim3 grid((2*INNER)/R1_BN, (NB*NKV)/R1_BM);   // (16, 520)
        gemm_kv_r1<<<grid, 256>>>();
    }

    // 5. attention (split-KV, fp16x2 ex2 softmax) + combine
    {
        dim3 grid(NB, NHEADS, SPLIT);
        attn_mma_kernel<<<grid, 128>>>();
        attn_combine<<<(NB*NLAT*INNER/2 + 255)/256, 256>>>();
    }

    // 6. out = ao @ Wout -> d_out (fp32)
    {
        dim3 grid(DIM/BN, (NB*NLAT)/BM);
        gemm_db<float><<<grid, 256, GEMM_SMEM>>>((const __half*)p_ao, (const __half*)p_wout,
                                                 out, NB*NLAT, DIM, INNER, 1.0f);
    }
}

// round 17
// speedup vs baseline: 1.3030x; 1.0172x over previous
#include <cuda_runtime.h>
#include <cuda_fp16.h>
#include <cstdint>

#define NB     16
#define NMEDIA 4096
#define NLAT   64
#define NKV    4160
#define DIM    1024
#define INNER  1024
#define NHEADS 16
#define DHEAD  64
#define SPLIT  5
#define TILES_PER 13   // 65 K-tiles of 64 / SPLIT

// ---------------- scratch (static device globals; no runtime allocation) ----------------
__device__ __half g_kvin [(size_t)NB*NKV*DIM];
__device__ __half g_lat16[(size_t)NB*NLAT*DIM];
__device__ __half g_q16  [(size_t)NB*NLAT*INNER];
__device__ __half g_kv16 [(size_t)NB*NKV*2*INNER];
__device__ __half g_ao16 [(size_t)NB*NLAT*INNER];
__device__ __half g_wq16 [(size_t)DIM*INNER];
__device__ __half g_wkv16[(size_t)DIM*2*INNER];    // Wkv fp16 [K][N]
__device__ __half g_wout16[(size_t)INNER*DIM];
__device__ float  g_opart[(size_t)SPLIT*NB*NLAT*INNER];
__device__ float  g_mlp  [(size_t)SPLIT*NB*NLAT*NHEADS*2];

// ---------------- helpers ----------------
__device__ __forceinline__ void cp_async16(uint32_t smem_dst, const void* gsrc) {
    asm volatile("cp.async.cg.shared.global [%0], [%1], 16;\n" :: "r"(smem_dst), "l"(gsrc));
}
__device__ __forceinline__ void cp_commit() { asm volatile("cp.async.commit_group;\n" ::); }
__device__ __forceinline__ void cp_wait1()  { asm volatile("cp.async.wait_group 1;\n" ::: "memory"); }
__device__ __forceinline__ void cp_wait0()  { asm volatile("cp.async.wait_group 0;\n" ::: "memory"); }

// ---------------- weight conversion fp32 -> fp16 (vectorized x4) ----------------
__global__ void cvt_weights(const float* __restrict__ Wq,
                            const float* __restrict__ Wkv,
                            const float* __restrict__ Wout) {
    int i4 = blockIdx.x * blockDim.x + threadIdx.x;   // one float4 per thread
    const int n1 = DIM*INNER/4;      // Wq in float4 units
    const int n2 = DIM*2*INNER/4;    // Wkv
    const int n3 = INNER*DIM/4;      // Wout

    const float* src;
    __half* dst;
    int idx;
    if (i4 < n1)            { src = Wq;   dst = g_wq16;   idx = i4; }
    else if (i4 < n1 + n2)  { src = Wkv;  dst = g_wkv16;  idx = i4 - n1; }
    else if (i4 < n1+n2+n3) { src = Wout; dst = g_wout16; idx = i4 - n1 - n2; }
    else return;

    float4 v = ((const float4*)src)[idx];
    __half2 h0 = __floats2half2_rn(v.x, v.y);
    __half2 h1 = __floats2half2_rn(v.z, v.w);
    uint2 st;
    st.x = *(uint32_t*)&h0;
    st.y = *(uint32_t*)&h1;
    ((uint2*)dst)[idx] = st;
}

// ---------------- fused layernorm (x and latents), vectorized float4 ----------------
__global__ void __launch_bounds__(256) ln_kernel(
    const float* __restrict__ x, const float* __restrict__ lat,
    const float* __restrict__ gm, const float* __restrict__ bm,
    const float* __restrict__ gl, const float* __restrict__ bl)
{
    int r  = blockIdx.x;
    int b  = r / NKV;
    int jj = r - b * NKV;
    bool isl = (jj >= NMEDIA);
    const float* src = isl ? lat + ((size_t)b*NLAT + (jj - NMEDIA))*DIM
                           : x   + ((size_t)b*NMEDIA + jj)*DIM;
    const float* g  = isl ? gl : gm;
    const float* be = isl ? bl : bm;

    int t = threadIdx.x;
    float4 u = ((const float4*)src)[t];     // 256 threads x 4 = 1024
    float s  = u.x + u.y + u.z + u.w;
    float s2 = u.x*u.x + u.y*u.y + u.z*u.z + u.w*u.w;
#pragma unroll
    for (int o = 16; o; o >>= 1) {
        s  += __shfl_xor_sync(0xffffffffu, s,  o);
        s2 += __shfl_xor_sync(0xffffffffu, s2, o);
    }
    __shared__ float rs[8], rs2[8];
    if ((t & 31) == 0) { rs[t >> 5] = s; rs2[t >> 5] = s2; }
    __syncthreads();
    float ts = 0.f, ts2 = 0.f;
#pragma unroll
    for (int w = 0; w < 8; w++) { ts += rs[w]; ts2 += rs2[w]; }
    float mu  = ts * (1.f/DIM);
    float inv = rsqrtf(ts2 * (1.f/DIM) - mu*mu + 1e-5f);

    float4 g4 = ((const float4*)g)[t];
    float4 b4 = ((const float4*)be)[t];
    __half2 h0 = __floats2half2_rn((u.x - mu) * inv * g4.x + b4.x,
                                   (u.y - mu) * inv * g4.y + b4.y);
    __half2 h1 = __floats2half2_rn((u.z - mu) * inv * g4.z + b4.z,
                                   (u.w - mu) * inv * g4.w + b4.w);
    uint2 st;
    st.x = *(uint32_t*)&h0;
    st.y = *(uint32_t*)&h1;

    ((uint2*)(g_kvin + (size_t)r * DIM))[t] = st;
    if (isl)
        ((uint2*)(g_lat16 + ((size_t)b*NLAT + (jj - NMEDIA))*DIM))[t] = st;
}

// ======== kv GEMM (R1/R13 design — empirical best: 969 µs @ tensor 47.3%) ========
// Sync LDG.128->STS.128, single-buffered smem, 128x128x32, 2 CTAs/SM, 8 warps.
#define R1_BM 128
#define R1_BN 128
#define R1_BK 32

__global__ void __launch_bounds__(256, 2) gemm_kv_r1() {
    __shared__ __half As[R1_BM][R1_BK + 8];    // 128 x 40
    __shared__ __half Bs[R1_BK][R1_BN + 8];    // 32 x 136

    const int tid  = threadIdx.x;
    const int warp = tid >> 5, lane = tid & 31;
    const int wm = (warp & 1) * 64;
    const int wn = (warp >> 1) * 32;
    const int bm0 = blockIdx.y * R1_BM;
    const int bn0 = blockIdx.x * R1_BN;
    const int K = DIM, N = 2*INNER;

    float acc[4][4][4];
#pragma unroll
    for (int a = 0; a < 4; a++)
#pragma unroll
        for (int b = 0; b < 4; b++)
#pragma unroll
            for (int c = 0; c < 4; c++) acc[a][b][c] = 0.f;

    const int arow = tid >> 2, acol = (tid & 3) * 8;    // A tile: 128 x 32
    const int brow = tid >> 4, bcol = (tid & 15) * 8;   // B tile: 32 x 128

    for (int k0 = 0; k0 < K; k0 += R1_BK) {
        const __half* ga = g_kvin + (size_t)(bm0 + arow) * K + (k0 + acol);
        *(uint4*)(&As[arow     ][acol]) = *(const uint4*)ga;
        *(uint4*)(&As[arow + 64][acol]) = *(const uint4*)(ga + (size_t)64 * K);
        const __half* gb = g_wkv16 + (size_t)(k0 + brow) * N + (bn0 + bcol);
        *(uint4*)(&Bs[brow     ][bcol]) = *(const uint4*)gb;
        *(uint4*)(&Bs[brow + 16][bcol]) = *(const uint4*)(gb + (size_t)16 * N);
        __syncthreads();

#pragma unroll
        for (int kc = 0; kc < R1_BK; kc += 16) {
            uint32_t af[4][4], bf[4][2];
#pragma unroll
            for (int mf = 0; mf < 4; mf++) {
                uint32_t ad = (uint32_t)__cvta_generic_to_shared(
                    &As[wm + mf*16 + (lane & 15)][kc + ((lane >> 4) << 3)]);
                asm volatile("ldmatrix.sync.aligned.m8n8.x4.shared.b16 {%0,%1,%2,%3}, [%4];"
                    : "=r"(af[mf][0]), "=r"(af[mf][1]), "=r"(af[mf][2]), "=r"(af[mf][3])
                    : "r"(ad) : "memory");
            }
#pragma unroll
            for (int nf = 0; nf < 4; nf++) {
                uint32_t bd = (uint32_t)__cvta_generic_to_shared(
                    &Bs[kc + (lane & 15)][wn + nf*8]);
                asm volatile("ldmatrix.sync.aligned.m8n8.x2.trans.shared.b16 {%0,%1}, [%2];"
                    : "=r"(bf[nf][0]), "=r"(bf[nf][1]) : "r"(bd) : "memory");
            }
#pragma unroll
            for (int mf = 0; mf < 4; mf++)
#pragma unroll
                for (int nf = 0; nf < 4; nf++) {
                    asm volatile(
                        "mma.sync.aligned.m16n8k16.row.col.f32.f16.f16.f32 "
                        "{%0,%1,%2,%3}, {%4,%5,%6,%7}, {%8,%9}, {%0,%1,%2,%3};"
                        : "+f"(acc[mf][nf][0]), "+f"(acc[mf][nf][1]),
                          "+f"(acc[mf][nf][2]), "+f"(acc[mf][nf][3])
                        : "r"(af[mf][0]), "r"(af[mf][1]), "r"(af[mf][2]), "r"(af[mf][3]),
                          "r"(bf[nf][0]), "r"(bf[nf][1]));
                }
        }
        __syncthreads();
    }

    const int grp = lane >> 2, tig = lane & 3;
#pragma unroll
    for (int mf = 0; mf < 4; mf++)
#pragma unroll
        for (int nf = 0; nf < 4; nf++) {
            int row = bm0 + wm + mf*16 + grp;
            int col = bn0 + wn + nf*8 + tig*2;
            *(__half2*)&g_kv16[(size_t)row * N + col] =
                __floats2half2_rn(acc[mf][nf][0], acc[mf][nf][1]);
            *(__half2*)&g_kv16[(size_t)(row + 8) * N + col] =
                __floats2half2_rn(acc[mf][nf][2], acc[mf][nf][3]);
        }
}

// ---------------- double-buffered mma.sync GEMM (q and out GEMMs, small) ----------------
#define BM 128
#define BN 128
#define BKG 64
#define AS_STRIDE 72
#define BS_STRIDE 136
#define GEMM_SMEM ((2*BM*AS_STRIDE + 2*BKG*BS_STRIDE) * (int)sizeof(__half))

template<typename OutT>
__global__ void __launch_bounds__(256) gemm_db(
    const __half* __restrict__ A, const __half* __restrict__ Bmat,
    OutT* __restrict__ C, int M, int N, int K, float alpha)
{
    extern __shared__ __half smh[];
    __half* As = smh;
    __half* Bs = smh + 2*BM*AS_STRIDE;

    const int tid  = threadIdx.x;
    const int warp = tid >> 5, lane = tid & 31;
    const int wm = (warp & 1) * 64;
    const int wn = (warp >> 1) * 32;
    const int bm0 = blockIdx.y * BM;
    const int bn0 = blockIdx.x * BN;

    float acc[4][4][4];
#pragma unroll
    for (int a = 0; a < 4; a++)
#pragma unroll
        for (int b = 0; b < 4; b++)
#pragma unroll
            for (int c = 0; c < 4; c++) acc[a][b][c] = 0.f;

    const int arow = tid >> 1, acb = (tid & 1) * 32;
    const int brow = tid >> 2, bcb = (tid & 3) * 32;
    const uint32_t sA = (uint32_t)__cvta_generic_to_shared(As);
    const uint32_t sB = (uint32_t)__cvta_generic_to_shared(Bs);

    auto issue = [&](int k0, int st) {
        const __half* ga = A + (size_t)(bm0 + arow) * K + (k0 + acb);
        uint32_t da = sA + ((st*BM + arow)*AS_STRIDE + acb) * 2;
#pragma unroll
        for (int c = 0; c < 4; c++) cp_async16(da + c*16, ga + c*8);
        const __half* gb = Bmat + (size_t)(k0 + brow) * N + (bn0 + bcb);
        uint32_t db = sB + ((st*BKG + brow)*BS_STRIDE + bcb) * 2;
#pragma unroll
        for (int c = 0; c < 4; c++) cp_async16(db + c*16, gb + c*8);
    };

    issue(0, 0);
    cp_commit();

    int stage = 0;
    for (int k0 = 0; k0 < K; k0 += BKG) {
        if (k0 + BKG < K) { issue(k0 + BKG, stage ^ 1); cp_commit(); cp_wait1(); }
        else              { cp_wait0(); }
        __syncthreads();

        const __half* as = As + (size_t)stage * BM * AS_STRIDE;
        const __half* bs = Bs + (size_t)stage * BKG * BS_STRIDE;

#pragma unroll
        for (int kc = 0; kc < BKG; kc += 16) {
            uint32_t af[4][4], bf[4][2];
#pragma unroll
            for (int mf = 0; mf < 4; mf++) {
                uint32_t ad = (uint32_t)__cvta_generic_to_shared(
                    &as[(wm + mf*16 + (lane & 15))*AS_STRIDE + kc + ((lane >> 4) << 3)]);
                asm volatile("ldmatrix.sync.aligned.m8n8.x4.shared.b16 {%0,%1,%2,%3}, [%4];"
                    : "=r"(af[mf][0]), "=r"(af[mf][1]), "=r"(af[mf][2]), "=r"(af[mf][3])
                    : "r"(ad) : "memory");
            }
#pragma unroll
            for (int nf = 0; nf < 4; nf++) {
                uint32_t bd = (uint32_t)__cvta_generic_to_shared(
                    &bs[(kc + (lane & 15))*BS_STRIDE + wn + nf*8]);
                asm volatile("ldmatrix.sync.aligned.m8n8.x2.trans.shared.b16 {%0,%1}, [%2];"
                    : "=r"(bf[nf][0]), "=r"(bf[nf][1]) : "r"(bd) : "memory");
            }
#pragma unroll
            for (int mf = 0; mf < 4; mf++)
#pragma unroll
                for (int nf = 0; nf < 4; nf++) {
                    asm volatile(
                        "mma.sync.aligned.m16n8k16.row.col.f32.f16.f16.f32 "
                        "{%0,%1,%2,%3}, {%4,%5,%6,%7}, {%8,%9}, {%0,%1,%2,%3};"
                        : "+f"(acc[mf][nf][0]), "+f"(acc[mf][nf][1]),
                          "+f"(acc[mf][nf][2]), "+f"(acc[mf][nf][3])
                        : "r"(af[mf][0]), "r"(af[mf][1]), "r"(af[mf][2]), "r"(af[mf][3]),
                          "r"(bf[nf][0]), "r"(bf[nf][1]));
                }
        }
        __syncthreads();
        stage ^= 1;
    }

    const int grp = lane >> 2, tig = lane & 3;
#pragma unroll
    for (int mf = 0; mf < 4; mf++)
#pragma unroll
        for (int nf = 0; nf < 4; nf++) {
            int row = bm0 + wm + mf*16 + grp;
            int col = bn0 + wn + nf*8 + tig*2;
            if constexpr (sizeof(OutT) == 2) {
                *(__half2*)&C[(size_t)row * N + col] =
                    __floats2half2_rn(acc[mf][nf][0]*alpha, acc[mf][nf][1]*alpha);
                *(__half2*)&C[(size_t)(row + 8) * N + col] =
                    __floats2half2_rn(acc[mf][nf][2]*alpha, acc[mf][nf][3]*alpha);
            } else {
                *(float2*)&C[(size_t)row * N + col] =
                    make_float2(acc[mf][nf][0]*alpha, acc[mf][nf][1]*alpha);
                *(float2*)&C[(size_t)(row + 8) * N + col] =
                    make_float2(acc[mf][nf][2]*alpha, acc[mf][nf][3]*alpha);
            }
        }
}

// ---------------- tensor-core flash attention, split-KV (fp16x2 ex2 softmax) ----------------
#define QS_STR 72

__global__ void __launch_bounds__(128) attn_mma_kernel() {
    __shared__ __half Qs[64][QS_STR];
    __shared__ __half Ks[2][64][QS_STR];
    __shared__ __half Vs[2][64][QS_STR];

    const int b = blockIdx.x, h = blockIdx.y, sp = blockIdx.z;
    const int tid = threadIdx.x;
    const int warp = tid >> 5, lane = tid & 31;
    const int grp = lane >> 2, tig = lane & 3;

    {
        int row = tid >> 1, cb = (tid & 1) * 32;
        const __half* q = g_q16 + ((size_t)(b*NLAT + row))*INNER + h*DHEAD + cb;
#pragma unroll
        for (int c = 0; c < 4; c++)
            *(uint4*)&Qs[row][cb + c*8] = *(const uint4*)(q + c*8);
    }
    __syncthreads();

    uint32_t qf[4][4];
#pragma unroll
    for (int kk = 0; kk < 4; kk++) {
        uint32_t ad = (uint32_t)__cvta_generic_to_shared(
            &Qs[warp*16 + (lane & 15)][kk*16 + ((lane >> 4) << 3)]);
        asm volatile("ldmatrix.sync.aligned.m8n8.x4.shared.b16 {%0,%1,%2,%3}, [%4];"
            : "=r"(qf[kk][0]), "=r"(qf[kk][1]), "=r"(qf[kk][2]), "=r"(qf[kk][3])
            : "r"(ad) : "memory");
    }

    const uint32_t sK = (uint32_t)__cvta_generic_to_shared(&Ks[0][0][0]);
    const uint32_t sV = (uint32_t)__cvta_generic_to_shared(&Vs[0][0][0]);
    const int ldr = tid >> 1, ldcb = (tid & 1) * 32;

    auto issue_kv = [&](int jt, int st) {
        size_t gbase = ((size_t)(b*NKV + jt*64 + ldr)) * (2*INNER) + h*DHEAD + ldcb;
        uint32_t dk = sK + ((st*64 + ldr)*QS_STR + ldcb) * 2;
        uint32_t dv = sV + ((st*64 + ldr)*QS_STR + ldcb) * 2;
#pragma unroll
        for (int c = 0; c < 4; c++) {
            cp_async16(dk + c*16, g_kv16 + gbase + c*8);
            cp_async16(dv + c*16, g_kv16 + gbase + INNER + c*8);
        }
    };

    const int t0 = sp * TILES_PER;
    issue_kv(t0, 0);
    cp_commit();

    float m0 = -1e30f, m1 = -1e30f, l0 = 0.f, l1 = 0.f;
    float of[8][4];
#pragma unroll
    for (int nf = 0; nf < 8; nf++)
#pragma unroll
        for (int c = 0; c < 4; c++) of[nf][c] = 0.f;

    const float L2E = 1.4426950408889634f;

    int stage = 0;
    for (int jt = 0; jt < TILES_PER; jt++) {
        if (jt + 1 < TILES_PER) { issue_kv(t0 + jt + 1, stage ^ 1); cp_commit(); cp_wait1(); }
        else                    { cp_wait0(); }
        __syncthreads();

        float sf[8][4];
#pragma unroll
        for (int nf = 0; nf < 8; nf++) {
            sf[nf][0] = sf[nf][1] = sf[nf][2] = sf[nf][3] = 0.f;
#pragma unroll
            for (int kk = 0; kk < 4; kk++) {
                uint32_t bd = (uint32_t)__cvta_generic_to_shared(
                    &Ks[stage][nf*8 + (lane & 7)][kk*16 + ((lane >> 3) & 1) * 8]);
                uint32_t b0, b1;
                asm volatile("ldmatrix.sync.aligned.m8n8.x2.shared.b16 {%0,%1}, [%2];"
                    : "=r"(b0), "=r"(b1) : "r"(bd) : "memory");
                asm volatile(
                    "mma.sync.aligned.m16n8k16.row.col.f32.f16.f16.f32 "
                    "{%0,%1,%2,%3}, {%4,%5,%6,%7}, {%8,%9}, {%0,%1,%2,%3};"
                    : "+f"(sf[nf][0]), "+f"(sf[nf][1]), "+f"(sf[nf][2]), "+f"(sf[nf][3])
                    : "r"(qf[kk][0]), "r"(qf[kk][1]), "r"(qf[kk][2]), "r"(qf[kk][3]),
                      "r"(b0), "r"(b1));
            }
        }

        float mx0 = -1e30f, mx1 = -1e30f;
#pragma unroll
        for (int nf = 0; nf < 8; nf++) {
            mx0 = fmaxf(mx0, fmaxf(sf[nf][0], sf[nf][1]));
            mx1 = fmaxf(mx1, fmaxf(sf[nf][2], sf[nf][3]));
        }
        mx0 = fmaxf(mx0, __shfl_xor_sync(0xffffffffu, mx0, 1));
        mx0 = fmaxf(mx0, __shfl_xor_sync(0xffffffffu, mx0, 2));
        mx1 = fmaxf(mx1, __shfl_xor_sync(0xffffffffu, mx1, 1));
        mx1 = fmaxf(mx1, __shfl_xor_sync(0xffffffffu, mx1, 2));

        float mn0 = fmaxf(m0, mx0), mn1 = fmaxf(m1, mx1);
        float sc0 = __expf(m0 - mn0), sc1 = __expf(m1 - mn1);

        uint32_t pa[8], pb[8];
        float ls0 = 0.f, ls1 = 0.f;
#pragma unroll
        for (int nf = 0; nf < 8; nf++) {
            __half2 ta = __floats2half2_rn((sf[nf][0] - mn0) * L2E, (sf[nf][1] - mn0) * L2E);
            __half2 tb = __floats2half2_rn((sf[nf][2] - mn1) * L2E, (sf[nf][3] - mn1) * L2E);
            uint32_t ua = *(uint32_t*)&ta, ub = *(uint32_t*)&tb;
            uint32_t ra, rb;
            asm("ex2.approx.f16x2 %0, %1;" : "=r"(ra) : "r"(ua));
            asm("ex2.approx.f16x2 %0, %1;" : "=r"(rb) : "r"(ub));
            pa[nf] = ra; pb[nf] = rb;
            float2 fa = __half22float2(*(__half2*)&ra);
            float2 fb = __half22float2(*(__half2*)&rb);
            ls0 += fa.x + fa.y;
            ls1 += fb.x + fb.y;
        }
        ls0 += __shfl_xor_sync(0xffffffffu, ls0, 1);
        ls0 += __shfl_xor_sync(0xffffffffu, ls0, 2);
        ls1 += __shfl_xor_sync(0xffffffffu, ls1, 1);
        ls1 += __shfl_xor_sync(0xffffffffu, ls1, 2);

        l0 = l0 * sc0 + ls0;
        l1 = l1 * sc1 + ls1;
        m0 = mn0; m1 = mn1;
#pragma unroll
        for (int nf = 0; nf < 8; nf++) {
            of[nf][0] *= sc0; of[nf][1] *= sc0;
            of[nf][2] *= sc1; of[nf][3] *= sc1;
        }

#pragma unroll
        for (int nf = 0; nf < 8; nf++) {
#pragma unroll
            for (int kk = 0; kk < 4; kk++) {
                uint32_t bd = (uint32_t)__cvta_generic_to_shared(
                    &Vs[stage][kk*16 + (lane & 15)][nf*8]);
                uint32_t b0, b1;
                asm volatile("ldmatrix.sync.aligned.m8n8.x2.trans.shared.b16 {%0,%1}, [%2];"
                    : "=r"(b0), "=r"(b1) : "r"(bd) : "memory");
                asm volatile(
                    "mma.sync.aligned.m16n8k16.row.col.f32.f16.f16.f32 "
                    "{%0,%1,%2,%3}, {%4,%5,%6,%7}, {%8,%9}, {%0,%1,%2,%3};"
                    : "+f"(of[nf][0]), "+f"(of[nf][1]), "+f"(of[nf][2]), "+f"(of[nf][3])
                    : "r"(pa[2*kk]), "r"(pb[2*kk]), "r"(pa[2*kk+1]), "r"(pb[2*kk+1]),
                      "r"(b0), "r"(b1));
            }
        }
        __syncthreads();
        stage ^= 1;
    }

    const int row0g = b*NLAT + warp*16 + grp;
    float* op0 = g_opart + ((size_t)sp*NB*NLAT + row0g)*INNER + h*DHEAD;
    float* op1 = op0 + (size_t)8*INNER;
#pragma unroll
    for (int nf = 0; nf < 8; nf++) {
        int col = nf*8 + tig*2;
        *(float2*)&op0[col] = make_float2(of[nf][0], of[nf][1]);
        *(float2*)&op1[col] = make_float2(of[nf][2], of[nf][3]);
    }
    if (tig == 0) {
        size_t i0 = (((size_t)sp*NB*NLAT + row0g)*NHEADS + h)*2;
        g_mlp[i0]   = m0; g_mlp[i0+1] = l0;
        size_t i1 = (((size_t)sp*NB*NLAT + row0g + 8)*NHEADS + h)*2;
        g_mlp[i1]   = m1; g_mlp[i1+1] = l1;
    }
}

// ---------------- split-KV combine ----------------
__global__ void __launch_bounds__(256) attn_combine() {
    int idx = blockIdx.x * 256 + threadIdx.x;
    int row = idx >> 9;
    int c2  = (idx & 511) * 2;
    int h   = c2 >> 6;

    float ms[SPLIT], ls[SPLIT];
    float M = -1e30f;
#pragma unroll
    for (int s = 0; s < SPLIT; s++) {
        size_t i = (((size_t)s*NB*NLAT + row)*NHEADS + h)*2;
        ms[s] = g_mlp[i]; ls[s] = g_mlp[i+1];
        M = fmaxf(M, ms[s]);
    }
    float L = 0.f, o0 = 0.f, o1 = 0.f;
#pragma unroll
    for (int s = 0; s < SPLIT; s++) {
        float w = __expf(ms[s] - M);
        L += ls[s] * w;
        float2 v = *(const float2*)&g_opart[((size_t)s*NB*NLAT + row)*INNER + c2];
        o0 += v.x * w; o1 += v.y * w;
    }
    float inv = 1.f / L;
    *(__half2*)&g_ao16[(size_t)row*INNER + c2] = __floats2half2_rn(o0*inv, o1*inv);
}

// ---------------- launch ----------------
extern "C" void kernel_launch(void* const* d_in, const int* in_sizes, int n_in,
                              void* d_out, int out_size) {
    const float* x    = (const float*)d_in[0];
    const float* lat  = (const float*)d_in[1];
    const float* gm   = (const float*)d_in[2];
    const float* bm   = (const float*)d_in[3];
    const float* gl   = (const float*)d_in[4];
    const float* bl   = (const float*)d_in[5];
    const float* Wq   = (const float*)d_in[6];
    const float* Wkv  = (const float*)d_in[7];
    const float* Wout = (const float*)d_in[8];
    float* out = (float*)d_out;

    void *p_lat, *p_q, *p_ao, *p_wq, *p_wout;
    cudaGetSymbolAddress(&p_lat,  g_lat16);
    cudaGetSymbolAddress(&p_q,    g_q16);
    cudaGetSymbolAddress(&p_ao,   g_ao16);
    cudaGetSymbolAddress(&p_wq,   g_wq16);
    cudaGetSymbolAddress(&p_wout, g_wout16);

    cudaFuncSetAttribute(gemm_db<__half>, cudaFuncAttributeMaxDynamicSharedMemorySize, GEMM_SMEM);
    cudaFuncSetAttribute(gemm_db<float>,  cudaFuncAttributeMaxDynamicSharedMemorySize, GEMM_SMEM);

    // 1. weights fp32 -> fp16 (vectorized x4: 1M threads cover 4M elements)
    cvt_weights<<<(1024*1024 + 255)/256, 256>>>(Wq, Wkv, Wout);

    // 2. layernorm (vectorized float4)
    ln_kernel<<<NB*NKV, 256>>>(x, lat, gm, bm, gl, bl);

    // 3. q = lat_ln @ Wq * d^-0.5
    {
        dim3 grid(INNER/BN, (NB*NLAT)/BM);
        gemm_db<__half><<<grid, 256, GEMM_SMEM>>>((const __half*)p_lat, (const __half*)p_wq,
                                                  (__half*)p_q, NB*NLAT, INNER, DIM, 0.125f);
    }

    // 4. kv GEMM — R13 empirical-best design (frozen)
    {
        dim3 grid((2*INNER)/R1_BN, (NB*NKV)/R1_BM);   // (16, 520)
        gemm_kv_r1<<<grid, 256>>>();
    }

    // 5. attention (split-KV, fp16x2 ex2 softmax) + combine
    {
        dim3 grid(NB, NHEADS, SPLIT);
        attn_mma_kernel<<<grid, 128>>>();
        attn_combine<<<(NB*NLAT*INNER/2 + 255)/256, 256>>>();
    }

    // 6. out = ao @ Wout -> d_out (fp32)
    {
        dim3 grid(DIM/BN, (NB*NLAT)/BM);
        gemm_db<float><<<grid, 256, GEMM_SMEM>>>((const __half*)p_ao, (const __half*)p_wout,
                                                 out, NB*NLAT, DIM, INNER, 1.0f);
    }
}